// round 17
// baseline (speedup 1.0000x reference)
#include <cuda_runtime.h>
#include <cuda_bf16.h>
#include <cuda_fp8.h>
#include <math.h>

// Problem constants
#define NN 8192
#define CH 32
#define NP (NN / 16)    // packed u32 words per adj row
#define KSP 16          // j-splits for gcn
#define JR (NN / KSP)   // 512 j per split

// ---------------- device scratch (no allocation allowed) ----------------
__device__ __align__(256) unsigned g_A[(long)NN * NP];          // 2-bit packed adj (16 MB)
__device__ __align__(256) unsigned char g_H8T[3L * CH * NN];    // e4m3 H^T [plane][c][j] (768 KB)
__device__ float g_P[(long)KSP * NN * CH];                      // k-split fp32 partials (16 MB)
__device__ float g_pool[256 * CH];                              // per-block pooling partials

// ---------------------------------------------------------------------------
// helper: store one (j-row, all c) of the three H planes as fp8 into the
// transpose buffer sT[3][32][36].
// ---------------------------------------------------------------------------
__device__ __forceinline__ void h8_store(unsigned char (*sT)[32][36],
                                         float a0, float a1, float a2,
                                         int c, int lr) {
    sT[0][c][lr] = (unsigned char)__nv_cvt_float_to_fp8(a0, __NV_SATFINITE, __NV_E4M3);
    sT[1][c][lr] = (unsigned char)__nv_cvt_float_to_fp8(a1, __NV_SATFINITE, __NV_E4M3);
    sT[2][c][lr] = (unsigned char)__nv_cvt_float_to_fp8(a2, __NV_SATFINITE, __NV_E4M3);
}

__device__ __forceinline__ void h8_writeout(unsigned char (*sT)[32][36],
                                            int tid, int j0) {
#pragma unroll
    for (int k = 0; k < 3; k++) {
        int id = tid + k * 256;                 // 0..767
        int r = id >> 3, w = id & 7;            // 96 rows x 8 words
        *(unsigned*)&g_H8T[(long)r * NN + j0 + w * 4] =
            *(const unsigned*)&sT[r >> 5][r & 31][w * 4];
    }
}

// ---------------------------------------------------------------------------
// prep: FUSED repack + hgen(layer 0), partitioned by blockIdx.x.
// ---------------------------------------------------------------------------
__global__ __launch_bounds__(256) void prep_kernel(const int* __restrict__ adj,
                                                   const float* __restrict__ V,
                                                   const float* __restrict__ w1,
                                                   const float* __restrict__ w2,
                                                   const float* __restrict__ w3) {
    __shared__ float sw[3][32][32];
    __shared__ float sZ[32][33];
    __shared__ unsigned char sT[3][32][36];
    const int tid = threadIdx.x;

    if (blockIdx.x >= 256) {
        const long idx = (long)(blockIdx.x - 256) * 256 + tid;  // 0 .. 4M-1
        const int4* src = (const int4*)(adj + idx * 16);
        unsigned w = 0;
#pragma unroll
        for (int q = 0; q < 4; q++) {
            int4 a = src[q];
            unsigned b = (unsigned)(a.x & 3) | ((unsigned)(a.y & 3) << 2) |
                         ((unsigned)(a.z & 3) << 4) | ((unsigned)(a.w & 3) << 6);
            w |= b << (q * 8);
        }
        g_A[idx] = w;
        return;
    }

#pragma unroll
    for (int q = 0; q < 4; q++) {
        int id = tid + q * 256;
        sw[0][id >> 5][id & 31] = w1[id];
        sw[1][id >> 5][id & 31] = w2[id];
        sw[2][id >> 5][id & 31] = w3[id];
    }
    const int c = tid & 31, w = tid >> 5;
    const int j0 = blockIdx.x * 32;
#pragma unroll
    for (int rr = 0; rr < 4; rr++) {
        const int lr = w * 4 + rr;
        sZ[lr][c] = V[(long)(j0 + lr) * CH + c];
    }
    __syncthreads();
#pragma unroll
    for (int rr = 0; rr < 4; rr++) {
        const int lr = w * 4 + rr;
        float a0 = 0.f, a1 = 0.f, a2 = 0.f;
#pragma unroll
        for (int d = 0; d < 32; d++) {
            float zd = sZ[lr][d];
            a0 += zd * sw[0][d][c];
            a1 += zd * sw[1][d][c];
            a2 += zd * sw[2][d][c];
        }
        h8_store(sT, a0, a1, a2, c, lr);
    }
    __syncthreads();
    h8_writeout(sT, tid, j0);
}

// ---------------------------------------------------------------------------
// hgen (layer 1): Z = relu(gb0 + sum_s P[s]); H_k = Z @ w_k -> fp8 transposed.
// ---------------------------------------------------------------------------
__global__ __launch_bounds__(256, 2) void hgen_kernel(const float* __restrict__ bias,
                                                      const float* __restrict__ w1,
                                                      const float* __restrict__ w2,
                                                      const float* __restrict__ w3) {
    __shared__ float sw[3][32][32];
    __shared__ float sZ[32][33];
    __shared__ unsigned char sT[3][32][36];
    const int tid = threadIdx.x;
#pragma unroll
    for (int q = 0; q < 4; q++) {
        int id = tid + q * 256;
        sw[0][id >> 5][id & 31] = w1[id];
        sw[1][id >> 5][id & 31] = w2[id];
        sw[2][id >> 5][id & 31] = w3[id];
    }
    const int c = tid & 31, w = tid >> 5;
    const int j0 = blockIdx.x * 32;
#pragma unroll
    for (int rr = 0; rr < 4; rr++) {
        const int lr = w * 4 + rr, row = j0 + lr;
        float s = 0.f;
#pragma unroll
        for (int p = 0; p < KSP; p++) s += g_P[((long)p * NN + row) * CH + c];
        sZ[lr][c] = fmaxf(bias[c] + s, 0.f);
    }
    __syncthreads();
#pragma unroll
    for (int rr = 0; rr < 4; rr++) {
        const int lr = w * 4 + rr;
        float a0 = 0.f, a1 = 0.f, a2 = 0.f;
#pragma unroll
        for (int d = 0; d < 32; d++) {
            float zd = sZ[lr][d];
            a0 += zd * sw[0][d][c];
            a1 += zd * sw[1][d][c];
            a2 += zd * sw[2][d][c];
        }
        h8_store(sT, a0, a1, a2, c, lr);
    }
    __syncthreads();
    h8_writeout(sT, tid, j0);
}

// ---------------------------------------------------------------------------
// gcn: masked matmul, FP8 mma m16n8k32. grid (64 m-tiles, KSP), 256 threads.
// A = three e4m3 0/1 mask planes built in registers from packed adj (byte
// extract + bit-spread + PRMT). B = e4m3 H^T from smem via conflict-free
// LDS.32 (row stride 144 -> lane bank = 4g+t, all distinct). f32 accum.
// ---------------------------------------------------------------------------
__device__ __forceinline__ void mma_fp8(float* c, const unsigned* a,
                                        unsigned b0, unsigned b1) {
    asm volatile(
        "mma.sync.aligned.m16n8k32.row.col.f32.e4m3.e4m3.f32 "
        "{%0,%1,%2,%3},{%4,%5,%6,%7},{%8,%9},{%0,%1,%2,%3};"
        : "+f"(c[0]), "+f"(c[1]), "+f"(c[2]), "+f"(c[3])
        : "r"(a[0]), "r"(a[1]), "r"(a[2]), "r"(a[3]), "r"(b0), "r"(b1));
}

// spread four 2-bit entries of a byte into four PRMT selector nibbles
__device__ __forceinline__ unsigned spread2(unsigned x) {
    return (x & 3u) | ((x << 2) & 0x30u) | ((x << 4) & 0x300u) | ((x << 6) & 0x3000u);
}

#define PLANE_STRIDE 4608           // 32 rows x 144 B
#define ROW_STRIDE 144

__global__ __launch_bounds__(256, 4) void gcn_kernel() {
    __shared__ __align__(16) unsigned char s_H8[3 * 32 * ROW_STRIDE];  // 13824 B

    const int tid = threadIdx.x;
    const int warp = tid >> 5, lane = tid & 31;
    const int g = lane >> 2, t = lane & 3;
    const int i0 = blockIdx.x * 128;
    const int ksp = blockIdx.y;
    const long jbase = (long)ksp * JR;

    float acc[16];
#pragma unroll
    for (int x = 0; x < 16; x++) acc[x] = 0.f;

    const int r0 = i0 + warp * 16 + g;
    const unsigned* ap0 = g_A + (long)r0 * NP + (jbase >> 4);  // row g
    const unsigned* ap1 = ap0 + 8L * NP;                       // row g+8
    const unsigned bsel = 0x4440u | (unsigned)t;               // byte-t extractor

    for (int jsb = 0; jsb < JR; jsb += 128) {
        __syncthreads();
        // stage H^T chunk: 96 rows x 128 B (dst stride 144), coalesced uint4
#pragma unroll
        for (int q = 0; q < 3; q++) {
            int id = tid + q * 256;                 // 0..767
            int row = id >> 3, w = id & 7;
            *(uint4*)&s_H8[row * ROW_STRIDE + w * 16] =
                *(const uint4*)(g_H8T + (long)row * NN + jbase + jsb + w * 16);
        }
        __syncthreads();

#pragma unroll
        for (int jo = 0; jo < 128; jo += 32) {
            const int jc = jsb + jo;
            const uint2 wg = *(const uint2*)(ap0 + (jc >> 4));   // row g,   32 j
            const uint2 wh = *(const uint2*)(ap1 + (jc >> 4));   // row g+8, 32 j

            // selector words for the 4 A-regs (shared by all 3 masks)
            unsigned s0 = spread2(__byte_perm(wg.x, 0, bsel));   // row g,   k 0..15
            unsigned s1 = spread2(__byte_perm(wh.x, 0, bsel));   // row g+8, k 0..15
            unsigned s2 = spread2(__byte_perm(wg.y, 0, bsel));   // row g,   k 16..31
            unsigned s3 = spread2(__byte_perm(wh.y, 0, bsel));   // row g+8, k 16..31

#pragma unroll
            for (int m = 0; m < 3; m++) {
                const unsigned SRC = 0x3800u << (8 * m);   // byte (m+1) = 0x38 (e4m3 1.0)
                unsigned A[4] = { __byte_perm(SRC, 0, s0), __byte_perm(SRC, 0, s1),
                                  __byte_perm(SRC, 0, s2), __byte_perm(SRC, 0, s3) };
#pragma unroll
                for (int nt = 0; nt < 4; nt++) {
                    const unsigned base =
                        (unsigned)(m * PLANE_STRIDE + (g + 8 * nt) * ROW_STRIDE + jo + 4 * t);
                    unsigned b0 = *(const unsigned*)&s_H8[base];        // k 0..15
                    unsigned b1 = *(const unsigned*)&s_H8[base + 16];   // k 16..31
                    mma_fp8(acc + nt * 4, A, b0, b1);
                }
            }
        }
    }

    // fp32 partials (deterministic; reduced downstream)
    float* P = g_P + ((long)ksp * NN + i0 + warp * 16) * CH;
#pragma unroll
    for (int nt = 0; nt < 4; nt++) {
        int c = nt * 8 + 2 * t;
        *(float2*)(P + (g)     * CH + c) = make_float2(acc[nt * 4 + 0], acc[nt * 4 + 1]);
        *(float2*)(P + (g + 8) * CH + c) = make_float2(acc[nt * 4 + 2], acc[nt * 4 + 3]);
    }
}

// ---------------------------------------------------------------------------
// finish2: pooled sums of relu(gb1 + sum_s P[s]). grid 256 x 256.
// ---------------------------------------------------------------------------
__global__ __launch_bounds__(256, 2) void finish2_kernel(const float* __restrict__ bias) {
    __shared__ float sred[8][32];
    const int c = threadIdx.x & 31, w = threadIdx.x >> 5;
    const int j0 = blockIdx.x * 32;
    const float b = bias[c];
    float local = 0.f;
#pragma unroll
    for (int rr = 0; rr < 4; rr++) {
        const int row = j0 + w * 4 + rr;
        float s = 0.f;
#pragma unroll
        for (int p = 0; p < KSP; p++) s += g_P[((long)p * NN + row) * CH + c];
        local += fmaxf(b + s, 0.f);
    }
    sred[w][c] = local;
    __syncthreads();
    if (w == 0) {
        float tt = sred[0][c];
#pragma unroll
        for (int q = 1; q < 8; q++) tt += sred[q][c];
        g_pool[blockIdx.x * 32 + c] = tt;
    }
}

// ---------------------------------------------------------------------------
// final: pool -> fc0(relu) -> fc1 -> sigmoid. 1 block, 256 threads.
// ---------------------------------------------------------------------------
__global__ void final_kernel(const float* __restrict__ fcW0, const float* __restrict__ fcb0,
                             const float* __restrict__ fcW1, const float* __restrict__ fcb1,
                             float* __restrict__ out) {
    __shared__ float sred[8][32];
    __shared__ float pool[32];
    const int c = threadIdx.x & 31, w = threadIdx.x >> 5;
    float s = 0.f;
    for (int i = 0; i < 32; i++) s += g_pool[(w * 32 + i) * 32 + c];
    sred[w][c] = s;
    __syncthreads();
    if (w == 0) {
        float p = sred[0][c];
#pragma unroll
        for (int q = 1; q < 8; q++) p += sred[q][c];
        pool[c] = p;
        __syncwarp();
        float o = fcb0[c];
#pragma unroll
        for (int d = 0; d < 32; d++) o += pool[d] * fcW0[c * 32 + d];
        o = fmaxf(o, 0.f);
        float v = o * fcW1[c];
#pragma unroll
        for (int off = 16; off; off >>= 1) v += __shfl_xor_sync(0xffffffffu, v, off);
        if (c == 0) out[0] = 1.f / (1.f + expf(-(v + fcb1[0])));
    }
}

// ---------------------------------------------------------------------------
extern "C" void kernel_launch(void* const* d_in, const int* in_sizes, int n_in,
                              void* d_out, int out_size) {
    (void)in_sizes; (void)n_in; (void)out_size;
    const float* V    = (const float*)d_in[0];
    const int*   adj  = (const int*)d_in[1];
    const float* w1_0 = (const float*)d_in[2];
    const float* w2_0 = (const float*)d_in[3];
    const float* w3_0 = (const float*)d_in[4];
    const float* gb_0 = (const float*)d_in[5];
    const float* w1_1 = (const float*)d_in[6];
    const float* w2_1 = (const float*)d_in[7];
    const float* w3_1 = (const float*)d_in[8];
    const float* gb_1 = (const float*)d_in[9];
    const float* fcW0 = (const float*)d_in[10];
    const float* fcb0 = (const float*)d_in[11];
    const float* fcW1 = (const float*)d_in[12];
    const float* fcb1 = (const float*)d_in[13];

    dim3 gG(64, KSP);

    prep_kernel<<<256 + NN * NP / 256, 256>>>(adj, V, w1_0, w2_0, w3_0);  // repack + H(L1)
    gcn_kernel<<<gG, 256>>>();                                 // layer-1 masked matmul
    hgen_kernel<<<256, 256>>>(gb_0, w1_1, w2_1, w3_1);         // Z=relu(..), H planes (L2)
    gcn_kernel<<<gG, 256>>>();                                 // layer-2 masked matmul
    finish2_kernel<<<256, 256>>>(gb_1);                        // relu+bias+pool partials
    final_kernel<<<1, 256>>>(fcW0, fcb0, fcW1, fcb1, (float*)d_out);
}